// round 1
// baseline (speedup 1.0000x reference)
#include <cuda_runtime.h>
#include <math.h>

#define NB    4
#define SEQ   2048
#define DM    1024
#define NH    16
#define DK    64
#define MROWS (NB*SEQ)   // 8192

// Scratch (allocation-free rule: device globals)
__device__ float g_q[(size_t)NB*SEQ*DM];
__device__ float g_k[(size_t)NB*SEQ*DM];
__device__ float g_v[(size_t)NB*SEQ*DM];
__device__ float g_attn[(size_t)NB*SEQ*DM];

// ---------------------------------------------------------------------------
// GEMM: C[M,N] = X[M,K] @ W[N,K]^T   (both row-major, K contiguous for both)
// BM=128, BN=64, BK=16, 256 threads, 8x4 per-thread micro-tile.
// ---------------------------------------------------------------------------
__global__ void __launch_bounds__(256) gemm_xwt(const float* __restrict__ X,
                                                const float* __restrict__ W,
                                                float* __restrict__ C,
                                                int M, int N, int K)
{
    __shared__ float As[16][132];  // [k][m], BM=128 + pad
    __shared__ float Bs[16][68];   // [k][n], BN=64  + pad

    const int bm = blockIdx.y * 128;
    const int bn = blockIdx.x * 64;
    const int t  = threadIdx.x;
    const int tx = t & 15;         // 0..15 -> 4 cols each
    const int ty = t >> 4;         // 0..15 -> 8 rows each

    float acc[8][4];
#pragma unroll
    for (int i = 0; i < 8; i++)
#pragma unroll
        for (int j = 0; j < 4; j++) acc[i][j] = 0.f;

    for (int k0 = 0; k0 < K; k0 += 16) {
        // load A tile: 128x16 floats = 512 float4, 2 per thread
#pragma unroll
        for (int i = 0; i < 2; i++) {
            int fidx = t + i * 256;          // 0..511
            int lm = fidx >> 2;              // 0..127
            int lk = (fidx & 3) * 4;         // 0,4,8,12
            float4 a = *(const float4*)&X[(size_t)(bm + lm) * K + k0 + lk];
            As[lk + 0][lm] = a.x; As[lk + 1][lm] = a.y;
            As[lk + 2][lm] = a.z; As[lk + 3][lm] = a.w;
        }
        // load B tile: 64x16 floats = 256 float4, 1 per thread
        {
            int lm = t >> 2;                 // 0..63
            int lk = (t & 3) * 4;
            float4 w = *(const float4*)&W[(size_t)(bn + lm) * K + k0 + lk];
            Bs[lk + 0][lm] = w.x; Bs[lk + 1][lm] = w.y;
            Bs[lk + 2][lm] = w.z; Bs[lk + 3][lm] = w.w;
        }
        __syncthreads();

#pragma unroll
        for (int kk = 0; kk < 16; kk++) {
            float av[8], bv[4];
#pragma unroll
            for (int i = 0; i < 8; i++) av[i] = As[kk][ty * 8 + i];
#pragma unroll
            for (int j = 0; j < 4; j++) bv[j] = Bs[kk][tx * 4 + j];
#pragma unroll
            for (int i = 0; i < 8; i++)
#pragma unroll
                for (int j = 0; j < 4; j++) acc[i][j] += av[i] * bv[j];
        }
        __syncthreads();
    }

#pragma unroll
    for (int i = 0; i < 8; i++) {
        float4 w4 = make_float4(acc[i][0], acc[i][1], acc[i][2], acc[i][3]);
        *(float4*)&C[(size_t)(bm + ty * 8 + i) * N + bn + tx * 4] = w4;
    }
}

// ---------------------------------------------------------------------------
// Causal flash attention over head-slices of [b, n, DM] layout.
// Block = (b, h, 64-row q-tile). 256 threads: thread t owns row r=t/4,
// column segment cseg=t%4 (16 of the 64 d / score columns).
// Q row kept in registers; K,V tiles in smem. Online softmax via shuffles
// (each row's 4 owner lanes are consecutive within a warp).
// ---------------------------------------------------------------------------
__global__ void __launch_bounds__(256) flash_kernel(const float* __restrict__ qg,
                                                    const float* __restrict__ kg,
                                                    const float* __restrict__ vg,
                                                    float* __restrict__ og)
{
    __shared__ float Ks[64 * 68];
    __shared__ float Vs[64 * 68];
    const int S = 68;

    const int qt   = blockIdx.x;     // q tile (0..31)
    const int h    = blockIdx.y;
    const int b    = blockIdx.z;
    const int t    = threadIdx.x;
    const int r    = t >> 2;         // row within tile, 0..63
    const int cseg = t & 3;          // column segment, 0..3
    const int lane = t & 31;
    const int qbase = qt * 64;

    // Q row -> registers, pre-scaled by 1/sqrt(DK)
    const float* qrow = qg + ((size_t)(b * SEQ + qbase + r)) * DM + h * DK;
    float qv[64];
#pragma unroll
    for (int dd = 0; dd < 16; dd++) {
        float4 a = ((const float4*)qrow)[dd];
        qv[4 * dd + 0] = a.x * 0.125f;
        qv[4 * dd + 1] = a.y * 0.125f;
        qv[4 * dd + 2] = a.z * 0.125f;
        qv[4 * dd + 3] = a.w * 0.125f;
    }

    float o[16];
#pragma unroll
    for (int j = 0; j < 16; j++) o[j] = 0.f;
    float m_i = -INFINITY, l_i = 0.f;

    const float* kptr = kg + (size_t)b * SEQ * DM + h * DK;
    const float* vptr = vg + (size_t)b * SEQ * DM + h * DK;

    for (int kt = 0; kt <= qt; kt++) {
        // load K,V tiles: 64 rows x 16 float4 each
#pragma unroll
        for (int i = 0; i < 4; i++) {
            int idx = t + i * 256;
            int row = idx >> 4;
            int c4  = idx & 15;
            *(float4*)&Ks[row * S + c4 * 4] =
                *(const float4*)(kptr + (size_t)(kt * 64 + row) * DM + c4 * 4);
            *(float4*)&Vs[row * S + c4 * 4] =
                *(const float4*)(vptr + (size_t)(kt * 64 + row) * DM + c4 * 4);
        }
        __syncthreads();

        // S tile: s[c] = q_r . k_{cseg*16+c}
        float s[16];
#pragma unroll
        for (int c = 0; c < 16; c++) {
            const float4* kr = (const float4*)&Ks[(cseg * 16 + c) * S];
            float acc = 0.f;
#pragma unroll
            for (int dd = 0; dd < 16; dd++) {
                float4 k4 = kr[dd];
                acc += qv[4 * dd + 0] * k4.x + qv[4 * dd + 1] * k4.y
                     + qv[4 * dd + 2] * k4.z + qv[4 * dd + 3] * k4.w;
            }
            s[c] = acc;
        }

        // causal mask on the diagonal tile
        if (kt == qt) {
#pragma unroll
            for (int c = 0; c < 16; c++)
                if (cseg * 16 + c > r) s[c] = -INFINITY;
        }

        // row max across 16 local + 4 lanes of this row
        float mx = s[0];
#pragma unroll
        for (int c = 1; c < 16; c++) mx = fmaxf(mx, s[c]);
        mx = fmaxf(mx, __shfl_xor_sync(0xffffffffu, mx, 1));
        mx = fmaxf(mx, __shfl_xor_sync(0xffffffffu, mx, 2));

        float m_new = fmaxf(m_i, mx);
        float corr  = __expf(m_i - m_new);   // exp(-inf)=0 on first tile
        float rs = 0.f;
#pragma unroll
        for (int c = 0; c < 16; c++) {
            s[c] = __expf(s[c] - m_new);
            rs += s[c];
        }
        rs += __shfl_xor_sync(0xffffffffu, rs, 1);
        rs += __shfl_xor_sync(0xffffffffu, rs, 2);
        l_i = l_i * corr + rs;
        m_i = m_new;
#pragma unroll
        for (int j = 0; j < 16; j++) o[j] *= corr;

        // O += P @ V  (fetch P values from sibling lanes via shuffle)
#pragma unroll
        for (int src = 0; src < 4; src++) {
#pragma unroll
            for (int c = 0; c < 16; c++) {
                float pv = __shfl_sync(0xffffffffu, s[c], (lane & 28) | src);
                const float4* vr = (const float4*)&Vs[(src * 16 + c) * S + cseg * 16];
                float4 v0 = vr[0], v1 = vr[1], v2 = vr[2], v3 = vr[3];
                o[0]  += pv * v0.x; o[1]  += pv * v0.y; o[2]  += pv * v0.z; o[3]  += pv * v0.w;
                o[4]  += pv * v1.x; o[5]  += pv * v1.y; o[6]  += pv * v1.z; o[7]  += pv * v1.w;
                o[8]  += pv * v2.x; o[9]  += pv * v2.y; o[10] += pv * v2.z; o[11] += pv * v2.w;
                o[12] += pv * v3.x; o[13] += pv * v3.y; o[14] += pv * v3.z; o[15] += pv * v3.w;
            }
        }
        __syncthreads();
    }

    const float inv = 1.f / l_i;
    float* orow = og + ((size_t)(b * SEQ + qbase + r)) * DM + h * DK + cseg * 16;
#pragma unroll
    for (int jj = 0; jj < 4; jj++) {
        float4 w4 = make_float4(o[4 * jj + 0] * inv, o[4 * jj + 1] * inv,
                                o[4 * jj + 2] * inv, o[4 * jj + 3] * inv);
        ((float4*)orow)[jj] = w4;
    }
}

// ---------------------------------------------------------------------------

extern "C" void kernel_launch(void* const* d_in, const int* in_sizes, int n_in,
                              void* d_out, int out_size)
{
    (void)in_sizes; (void)n_in; (void)out_size;
    const float* Q  = (const float*)d_in[0];
    const float* K  = (const float*)d_in[1];
    const float* V  = (const float*)d_in[2];
    const float* wq = (const float*)d_in[3];
    const float* wk = (const float*)d_in[4];
    const float* wv = (const float*)d_in[5];
    const float* wo = (const float*)d_in[6];
    float* out = (float*)d_out;

    float *gq, *gk, *gv, *ga;
    cudaGetSymbolAddress((void**)&gq, g_q);
    cudaGetSymbolAddress((void**)&gk, g_k);
    cudaGetSymbolAddress((void**)&gv, g_v);
    cudaGetSymbolAddress((void**)&ga, g_attn);

    dim3 ggrid(DM / 64, MROWS / 128);   // (16, 64)

    gemm_xwt<<<ggrid, 256>>>(Q, wq, gq, MROWS, DM, DM);
    gemm_xwt<<<ggrid, 256>>>(K, wk, gk, MROWS, DM, DM);
    gemm_xwt<<<ggrid, 256>>>(V, wv, gv, MROWS, DM, DM);

    flash_kernel<<<dim3(SEQ / 64, NH, NB), 256>>>(gq, gk, gv, ga);

    gemm_xwt<<<ggrid, 256>>>(ga, wo, out, MROWS, DM, DM);
}

// round 3
// speedup vs baseline: 1.0664x; 1.0664x over previous
#include <cuda_runtime.h>
#include <cstdint>
#include <math.h>

#define NB    4
#define SEQ   2048
#define DM    1024
#define NH    16
#define DK    64
#define MROWS (NB*SEQ)   // 8192

// Scratch (allocation-free rule: device globals)
__device__ float g_q[(size_t)NB*SEQ*DM];
__device__ float g_k[(size_t)NB*SEQ*DM];
__device__ float g_v[(size_t)NB*SEQ*DM];
__device__ float g_attn[(size_t)NB*SEQ*DM];

// ---------------------------------------------------------------------------
// tf32 helpers (baseline PTX — works on compute_103 without 'a' features)
// ---------------------------------------------------------------------------
__device__ __forceinline__ uint32_t f32_to_tf32(float x) {
    uint32_t r;
    asm("cvt.rna.tf32.f32 %0, %1;" : "=r"(r) : "f"(x));
    return r;
}

__device__ __forceinline__ void mma_tf32_16x8x8(float* c, const uint32_t* a,
                                                const uint32_t* b) {
    asm volatile(
        "mma.sync.aligned.m16n8k8.row.col.f32.tf32.tf32.f32 "
        "{%0,%1,%2,%3}, {%4,%5,%6,%7}, {%8,%9}, {%0,%1,%2,%3};"
        : "+f"(c[0]), "+f"(c[1]), "+f"(c[2]), "+f"(c[3])
        : "r"(a[0]), "r"(a[1]), "r"(a[2]), "r"(a[3]),
          "r"(b[0]), "r"(b[1]));
}

// ===========================================================================
// GEMM: C[M,N] = X[M,K] @ W[N,K]^T   (row-major fp32 in, tf32 mma, fp32 out)
// BM=128, BN=64, BK=32. 256 threads = 8 warps in 4x2; warp tile 32x32.
// ===========================================================================
#define GBM 128
#define GBN 64
#define GBK 32

__global__ void __launch_bounds__(256) gemm_mma(const float* __restrict__ X,
                                                const float* __restrict__ W,
                                                float* __restrict__ C,
                                                int M, int N, int K)
{
    __shared__ float As[GBK][GBM + 4];   // [k][m]
    __shared__ float Bs[GBK][GBN + 4];   // [k][n]

    const int t    = threadIdx.x;
    const int lane = t & 31;
    const int w    = t >> 5;
    const int bm   = blockIdx.y * GBM;
    const int bn   = blockIdx.x * GBN;
    const int wm   = (w >> 1) * 32;      // warp row offset (0,32,64,96)
    const int wn   = (w & 1) * 32;       // warp col offset (0,32)
    const int g    = lane >> 2;          // group id 0..7
    const int tg   = lane & 3;           // thread-in-group 0..3

    float acc[2][4][4];
#pragma unroll
    for (int ma = 0; ma < 2; ma++)
#pragma unroll
        for (int na = 0; na < 4; na++)
#pragma unroll
            for (int j = 0; j < 4; j++) acc[ma][na][j] = 0.f;

    for (int k0 = 0; k0 < K; k0 += GBK) {
        // A tile: 128 rows x 32 cols = 1024 float4, 4 per thread
#pragma unroll
        for (int i = 0; i < 4; i++) {
            int idx  = t + i * 256;
            int row  = idx >> 3;
            int col4 = (idx & 7) * 4;
            float4 v = *(const float4*)&X[(size_t)(bm + row) * K + k0 + col4];
            As[col4 + 0][row] = __uint_as_float(f32_to_tf32(v.x));
            As[col4 + 1][row] = __uint_as_float(f32_to_tf32(v.y));
            As[col4 + 2][row] = __uint_as_float(f32_to_tf32(v.z));
            As[col4 + 3][row] = __uint_as_float(f32_to_tf32(v.w));
        }
        // B tile: 64 rows x 32 cols = 512 float4, 2 per thread
#pragma unroll
        for (int i = 0; i < 2; i++) {
            int idx  = t + i * 256;
            int row  = idx >> 3;
            int col4 = (idx & 7) * 4;
            float4 v = *(const float4*)&W[(size_t)(bn + row) * K + k0 + col4];
            Bs[col4 + 0][row] = __uint_as_float(f32_to_tf32(v.x));
            Bs[col4 + 1][row] = __uint_as_float(f32_to_tf32(v.y));
            Bs[col4 + 2][row] = __uint_as_float(f32_to_tf32(v.z));
            Bs[col4 + 3][row] = __uint_as_float(f32_to_tf32(v.w));
        }
        __syncthreads();

#pragma unroll
        for (int ks = 0; ks < 4; ks++) {
            const int kk = ks * 8;
            uint32_t a[2][4], b[4][2];
#pragma unroll
            for (int ma = 0; ma < 2; ma++) {
                int r = wm + ma * 16 + g;
                a[ma][0] = __float_as_uint(As[kk + tg][r]);
                a[ma][1] = __float_as_uint(As[kk + tg][r + 8]);
                a[ma][2] = __float_as_uint(As[kk + tg + 4][r]);
                a[ma][3] = __float_as_uint(As[kk + tg + 4][r + 8]);
            }
#pragma unroll
            for (int na = 0; na < 4; na++) {
                int cl = wn + na * 8 + g;
                b[na][0] = __float_as_uint(Bs[kk + tg][cl]);
                b[na][1] = __float_as_uint(Bs[kk + tg + 4][cl]);
            }
#pragma unroll
            for (int ma = 0; ma < 2; ma++)
#pragma unroll
                for (int na = 0; na < 4; na++)
                    mma_tf32_16x8x8(acc[ma][na], a[ma], b[na]);
        }
        __syncthreads();
    }

    // Store: c0,c1 -> (row, col..col+1); c2,c3 -> (row+8, ...)
#pragma unroll
    for (int ma = 0; ma < 2; ma++) {
        int row0 = bm + wm + ma * 16 + g;
#pragma unroll
        for (int na = 0; na < 4; na++) {
            int col = bn + wn + na * 8 + tg * 2;
            float2 lo = make_float2(acc[ma][na][0], acc[ma][na][1]);
            float2 hi = make_float2(acc[ma][na][2], acc[ma][na][3]);
            *(float2*)&C[(size_t)row0 * N + col]       = lo;
            *(float2*)&C[(size_t)(row0 + 8) * N + col] = hi;
        }
    }
}

// ---------------------------------------------------------------------------
// Causal flash attention (SIMT fp32, unchanged from R1)
// ---------------------------------------------------------------------------
__global__ void __launch_bounds__(256) flash_kernel(const float* __restrict__ qg,
                                                    const float* __restrict__ kg,
                                                    const float* __restrict__ vg,
                                                    float* __restrict__ og)
{
    __shared__ float Ks[64 * 68];
    __shared__ float Vs[64 * 68];
    const int S = 68;

    const int qt   = blockIdx.x;
    const int h    = blockIdx.y;
    const int b    = blockIdx.z;
    const int t    = threadIdx.x;
    const int r    = t >> 2;
    const int cseg = t & 3;
    const int lane = t & 31;
    const int qbase = qt * 64;

    const float* qrow = qg + ((size_t)(b * SEQ + qbase + r)) * DM + h * DK;
    float qv[64];
#pragma unroll
    for (int dd = 0; dd < 16; dd++) {
        float4 a = ((const float4*)qrow)[dd];
        qv[4 * dd + 0] = a.x * 0.125f;
        qv[4 * dd + 1] = a.y * 0.125f;
        qv[4 * dd + 2] = a.z * 0.125f;
        qv[4 * dd + 3] = a.w * 0.125f;
    }

    float o[16];
#pragma unroll
    for (int j = 0; j < 16; j++) o[j] = 0.f;
    float m_i = -INFINITY, l_i = 0.f;

    const float* kptr = kg + (size_t)b * SEQ * DM + h * DK;
    const float* vptr = vg + (size_t)b * SEQ * DM + h * DK;

    for (int kt = 0; kt <= qt; kt++) {
#pragma unroll
        for (int i = 0; i < 4; i++) {
            int idx = t + i * 256;
            int row = idx >> 4;
            int c4  = idx & 15;
            *(float4*)&Ks[row * S + c4 * 4] =
                *(const float4*)(kptr + (size_t)(kt * 64 + row) * DM + c4 * 4);
            *(float4*)&Vs[row * S + c4 * 4] =
                *(const float4*)(vptr + (size_t)(kt * 64 + row) * DM + c4 * 4);
        }
        __syncthreads();

        float s[16];
#pragma unroll
        for (int c = 0; c < 16; c++) {
            const float4* kr = (const float4*)&Ks[(cseg * 16 + c) * S];
            float acc = 0.f;
#pragma unroll
            for (int dd = 0; dd < 16; dd++) {
                float4 k4 = kr[dd];
                acc += qv[4 * dd + 0] * k4.x + qv[4 * dd + 1] * k4.y
                     + qv[4 * dd + 2] * k4.z + qv[4 * dd + 3] * k4.w;
            }
            s[c] = acc;
        }

        if (kt == qt) {
#pragma unroll
            for (int c = 0; c < 16; c++)
                if (cseg * 16 + c > r) s[c] = -INFINITY;
        }

        float mx = s[0];
#pragma unroll
        for (int c = 1; c < 16; c++) mx = fmaxf(mx, s[c]);
        mx = fmaxf(mx, __shfl_xor_sync(0xffffffffu, mx, 1));
        mx = fmaxf(mx, __shfl_xor_sync(0xffffffffu, mx, 2));

        float m_new = fmaxf(m_i, mx);
        float corr  = __expf(m_i - m_new);
        float rs = 0.f;
#pragma unroll
        for (int c = 0; c < 16; c++) {
            s[c] = __expf(s[c] - m_new);
            rs += s[c];
        }
        rs += __shfl_xor_sync(0xffffffffu, rs, 1);
        rs += __shfl_xor_sync(0xffffffffu, rs, 2);
        l_i = l_i * corr + rs;
        m_i = m_new;
#pragma unroll
        for (int j = 0; j < 16; j++) o[j] *= corr;

#pragma unroll
        for (int src = 0; src < 4; src++) {
#pragma unroll
            for (int c = 0; c < 16; c++) {
                float pv = __shfl_sync(0xffffffffu, s[c], (lane & 28) | src);
                const float4* vr = (const float4*)&Vs[(src * 16 + c) * S + cseg * 16];
                float4 v0 = vr[0], v1 = vr[1], v2 = vr[2], v3 = vr[3];
                o[0]  += pv * v0.x; o[1]  += pv * v0.y; o[2]  += pv * v0.z; o[3]  += pv * v0.w;
                o[4]  += pv * v1.x; o[5]  += pv * v1.y; o[6]  += pv * v1.z; o[7]  += pv * v1.w;
                o[8]  += pv * v2.x; o[9]  += pv * v2.y; o[10] += pv * v2.z; o[11] += pv * v2.w;
                o[12] += pv * v3.x; o[13] += pv * v3.y; o[14] += pv * v3.z; o[15] += pv * v3.w;
            }
        }
        __syncthreads();
    }

    const float inv = 1.f / l_i;
    float* orow = og + ((size_t)(b * SEQ + qbase + r)) * DM + h * DK + cseg * 16;
#pragma unroll
    for (int jj = 0; jj < 4; jj++) {
        float4 w4 = make_float4(o[4 * jj + 0] * inv, o[4 * jj + 1] * inv,
                                o[4 * jj + 2] * inv, o[4 * jj + 3] * inv);
        ((float4*)orow)[jj] = w4;
    }
}

// ---------------------------------------------------------------------------

extern "C" void kernel_launch(void* const* d_in, const int* in_sizes, int n_in,
                              void* d_out, int out_size)
{
    (void)in_sizes; (void)n_in; (void)out_size;
    const float* Q  = (const float*)d_in[0];
    const float* K  = (const float*)d_in[1];
    const float* V  = (const float*)d_in[2];
    const float* wq = (const float*)d_in[3];
    const float* wk = (const float*)d_in[4];
    const float* wv = (const float*)d_in[5];
    const float* wo = (const float*)d_in[6];
    float* out = (float*)d_out;

    float *gq, *gk, *gv, *ga;
    cudaGetSymbolAddress((void**)&gq, g_q);
    cudaGetSymbolAddress((void**)&gk, g_k);
    cudaGetSymbolAddress((void**)&gv, g_v);
    cudaGetSymbolAddress((void**)&ga, g_attn);

    dim3 ggrid(DM / GBN, MROWS / GBM);   // (16, 64)

    gemm_mma<<<ggrid, 256>>>(Q, wq, gq, MROWS, DM, DM);
    gemm_mma<<<ggrid, 256>>>(K, wk, gk, MROWS, DM, DM);
    gemm_mma<<<ggrid, 256>>>(V, wv, gv, MROWS, DM, DM);

    flash_kernel<<<dim3(SEQ / 64, NH, NB), 256>>>(gq, gk, gv, ga);

    gemm_mma<<<ggrid, 256>>>(ga, wo, out, MROWS, DM, DM);
}

// round 4
// speedup vs baseline: 5.2369x; 4.9108x over previous
#include <cuda_runtime.h>
#include <cstdint>
#include <math.h>

#define NB    4
#define SEQ   2048
#define DM    1024
#define NH    16
#define DK    64
#define MROWS (NB*SEQ)   // 8192

// Scratch (allocation-free rule: device globals)
__device__ float g_q[(size_t)NB*SEQ*DM];
__device__ float g_k[(size_t)NB*SEQ*DM];
__device__ float g_v[(size_t)NB*SEQ*DM];
__device__ float g_attn[(size_t)NB*SEQ*DM];

// ---------------------------------------------------------------------------
// tf32 helpers (baseline PTX — works on compute_103 without 'a' features)
// ---------------------------------------------------------------------------
__device__ __forceinline__ uint32_t f32_to_tf32(float x) {
    uint32_t r;
    asm("cvt.rna.tf32.f32 %0, %1;" : "=r"(r) : "f"(x));
    return r;
}

__device__ __forceinline__ void mma_tf32_16x8x8(float* c, const uint32_t* a,
                                                const uint32_t* b) {
    asm volatile(
        "mma.sync.aligned.m16n8k8.row.col.f32.tf32.tf32.f32 "
        "{%0,%1,%2,%3}, {%4,%5,%6,%7}, {%8,%9}, {%0,%1,%2,%3};"
        : "+f"(c[0]), "+f"(c[1]), "+f"(c[2]), "+f"(c[3])
        : "r"(a[0]), "r"(a[1]), "r"(a[2]), "r"(a[3]),
          "r"(b[0]), "r"(b[1]));
}

// ===========================================================================
// GEMM: C[M,N] = X[M,K] @ W[N,K]^T   (row-major fp32 in, tf32 mma, fp32 out)
// BM=128, BN=64, BK=32. 256 threads = 8 warps in 4x2; warp tile 32x32.
// ===========================================================================
#define GBM 128
#define GBN 64
#define GBK 32

__global__ void __launch_bounds__(256) gemm_mma(const float* __restrict__ X,
                                                const float* __restrict__ W,
                                                float* __restrict__ C,
                                                int M, int N, int K)
{
    __shared__ float As[GBK][GBM + 4];   // [k][m]
    __shared__ float Bs[GBK][GBN + 4];   // [k][n]

    const int t    = threadIdx.x;
    const int lane = t & 31;
    const int w    = t >> 5;
    const int bm   = blockIdx.y * GBM;
    const int bn   = blockIdx.x * GBN;
    const int wm   = (w >> 1) * 32;
    const int wn   = (w & 1) * 32;
    const int g    = lane >> 2;
    const int tg   = lane & 3;

    float acc[2][4][4];
#pragma unroll
    for (int ma = 0; ma < 2; ma++)
#pragma unroll
        for (int na = 0; na < 4; na++)
#pragma unroll
            for (int j = 0; j < 4; j++) acc[ma][na][j] = 0.f;

    for (int k0 = 0; k0 < K; k0 += GBK) {
#pragma unroll
        for (int i = 0; i < 4; i++) {
            int idx  = t + i * 256;
            int row  = idx >> 3;
            int col4 = (idx & 7) * 4;
            float4 v = *(const float4*)&X[(size_t)(bm + row) * K + k0 + col4];
            As[col4 + 0][row] = __uint_as_float(f32_to_tf32(v.x));
            As[col4 + 1][row] = __uint_as_float(f32_to_tf32(v.y));
            As[col4 + 2][row] = __uint_as_float(f32_to_tf32(v.z));
            As[col4 + 3][row] = __uint_as_float(f32_to_tf32(v.w));
        }
#pragma unroll
        for (int i = 0; i < 2; i++) {
            int idx  = t + i * 256;
            int row  = idx >> 3;
            int col4 = (idx & 7) * 4;
            float4 v = *(const float4*)&W[(size_t)(bn + row) * K + k0 + col4];
            Bs[col4 + 0][row] = __uint_as_float(f32_to_tf32(v.x));
            Bs[col4 + 1][row] = __uint_as_float(f32_to_tf32(v.y));
            Bs[col4 + 2][row] = __uint_as_float(f32_to_tf32(v.z));
            Bs[col4 + 3][row] = __uint_as_float(f32_to_tf32(v.w));
        }
        __syncthreads();

#pragma unroll
        for (int ks = 0; ks < 4; ks++) {
            const int kk = ks * 8;
            uint32_t a[2][4], b[4][2];
#pragma unroll
            for (int ma = 0; ma < 2; ma++) {
                int r = wm + ma * 16 + g;
                a[ma][0] = __float_as_uint(As[kk + tg][r]);
                a[ma][1] = __float_as_uint(As[kk + tg][r + 8]);
                a[ma][2] = __float_as_uint(As[kk + tg + 4][r]);
                a[ma][3] = __float_as_uint(As[kk + tg + 4][r + 8]);
            }
#pragma unroll
            for (int na = 0; na < 4; na++) {
                int cl = wn + na * 8 + g;
                b[na][0] = __float_as_uint(Bs[kk + tg][cl]);
                b[na][1] = __float_as_uint(Bs[kk + tg + 4][cl]);
            }
#pragma unroll
            for (int ma = 0; ma < 2; ma++)
#pragma unroll
                for (int na = 0; na < 4; na++)
                    mma_tf32_16x8x8(acc[ma][na], a[ma], b[na]);
        }
        __syncthreads();
    }

#pragma unroll
    for (int ma = 0; ma < 2; ma++) {
        int row0 = bm + wm + ma * 16 + g;
#pragma unroll
        for (int na = 0; na < 4; na++) {
            int col = bn + wn + na * 8 + tg * 2;
            float2 lo = make_float2(acc[ma][na][0], acc[ma][na][1]);
            float2 hi = make_float2(acc[ma][na][2], acc[ma][na][3]);
            *(float2*)&C[(size_t)row0 * N + col]       = lo;
            *(float2*)&C[(size_t)(row0 + 8) * N + col] = hi;
        }
    }
}

// ===========================================================================
// Causal flash attention with mma.sync tf32.
// Block = 64 q-rows x (64-key tiles), 4 warps; warp owns 16 q-rows.
// Ks[64][68]: K tile for QK^T, then reused for P (after sync).
// Vs[64][72]: V tile (pad 72 -> conflict-free PV B-loads).
// ===========================================================================
__global__ void __launch_bounds__(128) flash_mma(const float* __restrict__ qg,
                                                 const float* __restrict__ kg,
                                                 const float* __restrict__ vg,
                                                 float* __restrict__ og)
{
    __shared__ uint32_t Ks[64][68];   // K tile / Q staging / P tile
    __shared__ uint32_t Vs[64][72];   // V tile

    const int qt   = blockIdx.x;
    const int h    = blockIdx.y;
    const int b    = blockIdx.z;
    const int t    = threadIdx.x;
    const int lane = t & 31;
    const int w    = t >> 5;
    const int g    = lane >> 2;       // 0..7
    const int tg   = lane & 3;        // 0..3
    const int r0   = w * 16 + g;      // local q row (this thread, low)
    const int r1   = r0 + 8;          // local q row (high)

    const float* qb = qg + ((size_t)(b * SEQ + qt * 64)) * DM + h * DK;
    const float* kb = kg + (size_t)b * SEQ * DM + h * DK;
    const float* vb = vg + (size_t)b * SEQ * DM + h * DK;

    // ---- stage Q (scaled, tf32) through Ks, then extract A-fragments ----
#pragma unroll
    for (int i = 0; i < 8; i++) {
        int idx = t + i * 128;          // float4 slot 0..1023
        int row = idx >> 4;
        int c4  = (idx & 15) * 4;
        float4 v = *(const float4*)(qb + (size_t)row * DM + c4);
        *(uint4*)&Ks[row][c4] = make_uint4(f32_to_tf32(v.x * 0.125f),
                                           f32_to_tf32(v.y * 0.125f),
                                           f32_to_tf32(v.z * 0.125f),
                                           f32_to_tf32(v.w * 0.125f));
    }
    __syncthreads();

    uint32_t qa[8][4];
#pragma unroll
    for (int ka = 0; ka < 8; ka++) {
        qa[ka][0] = Ks[r0][8 * ka + tg];
        qa[ka][1] = Ks[r1][8 * ka + tg];
        qa[ka][2] = Ks[r0][8 * ka + tg + 4];
        qa[ka][3] = Ks[r1][8 * ka + tg + 4];
    }

    float oacc[8][4];
#pragma unroll
    for (int na = 0; na < 8; na++)
#pragma unroll
        for (int j = 0; j < 4; j++) oacc[na][j] = 0.f;
    float m0 = -1e30f, m1 = -1e30f, l0 = 0.f, l1 = 0.f;

    for (int kt = 0; kt <= qt; kt++) {
        __syncthreads();   // prior readers of Ks/Vs done (incl. Q extraction)

        // ---- load K, V tiles (tf32) ----
#pragma unroll
        for (int i = 0; i < 8; i++) {
            int idx = t + i * 128;
            int row = idx >> 4;
            int c4  = (idx & 15) * 4;
            const float* kp = kb + (size_t)(kt * 64 + row) * DM + c4;
            const float* vp = vb + (size_t)(kt * 64 + row) * DM + c4;
            float4 kv = *(const float4*)kp;
            float4 vv = *(const float4*)vp;
            *(uint4*)&Ks[row][c4] = make_uint4(f32_to_tf32(kv.x), f32_to_tf32(kv.y),
                                               f32_to_tf32(kv.z), f32_to_tf32(kv.w));
            *(uint4*)&Vs[row][c4] = make_uint4(f32_to_tf32(vv.x), f32_to_tf32(vv.y),
                                               f32_to_tf32(vv.z), f32_to_tf32(vv.w));
        }
        __syncthreads();

        // ---- S = Q @ K^T  (8 n-atoms x 8 k-atoms) ----
        float sacc[8][4];
#pragma unroll
        for (int na = 0; na < 8; na++)
#pragma unroll
            for (int j = 0; j < 4; j++) sacc[na][j] = 0.f;

#pragma unroll
        for (int ka = 0; ka < 8; ka++) {
#pragma unroll
            for (int na = 0; na < 8; na++) {
                uint32_t bf[2];
                bf[0] = Ks[8 * na + g][8 * ka + tg];
                bf[1] = Ks[8 * na + g][8 * ka + tg + 4];
                mma_tf32_16x8x8(sacc[na], qa[ka], bf);
            }
        }

        // ---- causal mask on diagonal tile ----
        if (kt == qt) {
#pragma unroll
            for (int na = 0; na < 8; na++) {
                int c0 = 8 * na + 2 * tg;
                if (c0     > r0) sacc[na][0] = -1e30f;
                if (c0 + 1 > r0) sacc[na][1] = -1e30f;
                if (c0     > r1) sacc[na][2] = -1e30f;
                if (c0 + 1 > r1) sacc[na][3] = -1e30f;
            }
        }

        // ---- online softmax (rows r0, r1) ----
        float mx0 = -1e30f, mx1 = -1e30f;
#pragma unroll
        for (int na = 0; na < 8; na++) {
            mx0 = fmaxf(mx0, fmaxf(sacc[na][0], sacc[na][1]));
            mx1 = fmaxf(mx1, fmaxf(sacc[na][2], sacc[na][3]));
        }
        mx0 = fmaxf(mx0, __shfl_xor_sync(0xffffffffu, mx0, 1));
        mx0 = fmaxf(mx0, __shfl_xor_sync(0xffffffffu, mx0, 2));
        mx1 = fmaxf(mx1, __shfl_xor_sync(0xffffffffu, mx1, 1));
        mx1 = fmaxf(mx1, __shfl_xor_sync(0xffffffffu, mx1, 2));

        float m0n = fmaxf(m0, mx0);
        float m1n = fmaxf(m1, mx1);
        float c0f = __expf(m0 - m0n);
        float c1f = __expf(m1 - m1n);
        float s0 = 0.f, s1 = 0.f;
#pragma unroll
        for (int na = 0; na < 8; na++) {
            sacc[na][0] = __expf(sacc[na][0] - m0n);
            sacc[na][1] = __expf(sacc[na][1] - m0n);
            sacc[na][2] = __expf(sacc[na][2] - m1n);
            sacc[na][3] = __expf(sacc[na][3] - m1n);
            s0 += sacc[na][0] + sacc[na][1];
            s1 += sacc[na][2] + sacc[na][3];
        }
        s0 += __shfl_xor_sync(0xffffffffu, s0, 1);
        s0 += __shfl_xor_sync(0xffffffffu, s0, 2);
        s1 += __shfl_xor_sync(0xffffffffu, s1, 1);
        s1 += __shfl_xor_sync(0xffffffffu, s1, 2);
        l0 = l0 * c0f + s0;
        l1 = l1 * c1f + s1;
        m0 = m0n;
        m1 = m1n;
#pragma unroll
        for (int na = 0; na < 8; na++) {
            oacc[na][0] *= c0f; oacc[na][1] *= c0f;
            oacc[na][2] *= c1f; oacc[na][3] *= c1f;
        }

        // ---- P -> smem (reuse Ks) ----
        __syncthreads();   // all warps done reading K
#pragma unroll
        for (int na = 0; na < 8; na++) {
            int cc = 8 * na + 2 * tg;
            *(uint2*)&Ks[r0][cc] = make_uint2(f32_to_tf32(sacc[na][0]),
                                              f32_to_tf32(sacc[na][1]));
            *(uint2*)&Ks[r1][cc] = make_uint2(f32_to_tf32(sacc[na][2]),
                                              f32_to_tf32(sacc[na][3]));
        }
        __syncthreads();

        // ---- O += P @ V ----
#pragma unroll
        for (int ka = 0; ka < 8; ka++) {
            uint32_t pa[4];
            pa[0] = Ks[r0][8 * ka + tg];
            pa[1] = Ks[r1][8 * ka + tg];
            pa[2] = Ks[r0][8 * ka + tg + 4];
            pa[3] = Ks[r1][8 * ka + tg + 4];
#pragma unroll
            for (int na = 0; na < 8; na++) {
                uint32_t bf[2];
                bf[0] = Vs[8 * ka + tg][8 * na + g];
                bf[1] = Vs[8 * ka + tg + 4][8 * na + g];
                mma_tf32_16x8x8(oacc[na], pa, bf);
            }
        }
    }

    // ---- finalize and store ----
    float inv0 = 1.f / l0;
    float inv1 = 1.f / l1;
    float* ob = og + ((size_t)(b * SEQ + qt * 64)) * DM + h * DK;
#pragma unroll
    for (int na = 0; na < 8; na++) {
        int col = 8 * na + 2 * tg;
        *(float2*)(ob + (size_t)r0 * DM + col) =
            make_float2(oacc[na][0] * inv0, oacc[na][1] * inv0);
        *(float2*)(ob + (size_t)r1 * DM + col) =
            make_float2(oacc[na][2] * inv1, oacc[na][3] * inv1);
    }
}

// ---------------------------------------------------------------------------

extern "C" void kernel_launch(void* const* d_in, const int* in_sizes, int n_in,
                              void* d_out, int out_size)
{
    (void)in_sizes; (void)n_in; (void)out_size;
    const float* Q  = (const float*)d_in[0];
    const float* K  = (const float*)d_in[1];
    const float* V  = (const float*)d_in[2];
    const float* wq = (const float*)d_in[3];
    const float* wk = (const float*)d_in[4];
    const float* wv = (const float*)d_in[5];
    const float* wo = (const float*)d_in[6];
    float* out = (float*)d_out;

    float *gq, *gk, *gv, *ga;
    cudaGetSymbolAddress((void**)&gq, g_q);
    cudaGetSymbolAddress((void**)&gk, g_k);
    cudaGetSymbolAddress((void**)&gv, g_v);
    cudaGetSymbolAddress((void**)&ga, g_attn);

    dim3 ggrid(DM / GBN, MROWS / GBM);   // (16, 64)

    gemm_mma<<<ggrid, 256>>>(Q, wq, gq, MROWS, DM, DM);
    gemm_mma<<<ggrid, 256>>>(K, wk, gk, MROWS, DM, DM);
    gemm_mma<<<ggrid, 256>>>(V, wv, gv, MROWS, DM, DM);

    flash_mma<<<dim3(SEQ / 64, NH, NB), 128>>>(gq, gk, gv, ga);

    gemm_mma<<<ggrid, 256>>>(ga, wo, out, MROWS, DM, DM);
}

// round 7
// speedup vs baseline: 7.4837x; 1.4290x over previous
#include <cuda_runtime.h>
#include <cstdint>
#include <math.h>

#define NB    4
#define SEQ   2048
#define DM    1024
#define NH    16
#define DK    64
#define MROWS (NB*SEQ)   // 8192

// Scratch (allocation-free rule: device globals)
__device__ float g_q[(size_t)NB*SEQ*DM];
__device__ float g_k[(size_t)NB*SEQ*DM];
__device__ float g_v[(size_t)NB*SEQ*DM];
__device__ float g_attn[(size_t)NB*SEQ*DM];

// ---------------------------------------------------------------------------
// tf32 / cp.async helpers (baseline PTX — works on compute_103)
// ---------------------------------------------------------------------------
__device__ __forceinline__ uint32_t f32_to_tf32(float x) {
    uint32_t r;
    asm("cvt.rna.tf32.f32 %0, %1;" : "=r"(r) : "f"(x));
    return r;
}

__device__ __forceinline__ void mma_tf32_16x8x8(float* c, const uint32_t* a,
                                                const uint32_t* b) {
    asm volatile(
        "mma.sync.aligned.m16n8k8.row.col.f32.tf32.tf32.f32 "
        "{%0,%1,%2,%3}, {%4,%5,%6,%7}, {%8,%9}, {%0,%1,%2,%3};"
        : "+f"(c[0]), "+f"(c[1]), "+f"(c[2]), "+f"(c[3])
        : "r"(a[0]), "r"(a[1]), "r"(a[2]), "r"(a[3]),
          "r"(b[0]), "r"(b[1]));
}

__device__ __forceinline__ uint32_t smem_u32(const void* p) {
    uint32_t a;
    asm("{ .reg .u64 t; cvta.to.shared.u64 t, %1; cvt.u32.u64 %0, t; }"
        : "=r"(a) : "l"(p));
    return a;
}

__device__ __forceinline__ void cp_async16(uint32_t saddr, const void* gptr) {
    asm volatile("cp.async.cg.shared.global [%0], [%1], 16;"
                 :: "r"(saddr), "l"(gptr));
}
__device__ __forceinline__ void cp_commit() {
    asm volatile("cp.async.commit_group;");
}
template <int N>
__device__ __forceinline__ void cp_wait() {
    asm volatile("cp.async.wait_group %0;" :: "n"(N));
}

// ===========================================================================
// Pipelined tf32 GEMM: C[M,N] = X[M,K] @ W[N,K]^T
// BM=128, BN=128, BK=32; 256 threads = 8 warps (2x4); warp tile 64x32.
// cp.async double buffer, raw fp32 in smem [m][k] pitch 36, cvt at frag load.
// blockIdx.z selects (X,W,C) triple -> fused QKV projection launch.
// ===========================================================================
#define GBM 128
#define GBN 128
#define GBK 32
#define RPF 36                         // row pitch in floats
#define RPB (RPF * 4)                  // row pitch in bytes (144)
#define TILE_B (128 * RPB)             // one tile: 18432 bytes
#define SM_A(p) ((p) * TILE_B)
#define SM_B(p) (2 * TILE_B + (p) * TILE_B)
#define GEMM_SMEM (4 * TILE_B)         // 73728 bytes

__global__ void __launch_bounds__(256) gemm_pipe(
    const float* __restrict__ X0, const float* __restrict__ X1,
    const float* __restrict__ X2,
    const float* __restrict__ W0, const float* __restrict__ W1,
    const float* __restrict__ W2,
    float* __restrict__ C0, float* __restrict__ C1, float* __restrict__ C2,
    int M, int N, int K)
{
    extern __shared__ char smem[];
    const uint32_t sbase = smem_u32(smem);

    const float* X = X0; const float* W = W0; float* C = C0;
    if (blockIdx.z == 1) { X = X1; W = W1; C = C1; }
    else if (blockIdx.z == 2) { X = X2; W = W2; C = C2; }

    const int t    = threadIdx.x;
    const int lane = t & 31;
    const int w    = t >> 5;
    const int bm   = blockIdx.y * GBM;
    const int bn   = blockIdx.x * GBN;
    const int wm   = (w >> 2) * 64;        // 0 or 64
    const int wn   = (w & 3) * 32;         // 0,32,64,96
    const int g    = lane >> 2;            // 0..7
    const int tg   = lane & 3;             // 0..3

    // per-thread cp.async source/dest: 2 threads per row; even thread loads
    // chunks 0-3 (bytes 0-63), odd thread loads chunks 4-7 (bytes 64-127).
    const int crow  = t >> 1;              // 0..127
    const int cbase = (t & 1) * 4;         // chunk base: 0 or 4

    float acc[4][4][4];
#pragma unroll
    for (int ma = 0; ma < 4; ma++)
#pragma unroll
        for (int na = 0; na < 4; na++)
#pragma unroll
            for (int j = 0; j < 4; j++) acc[ma][na][j] = 0.f;

    const int nchunks = K / GBK;           // 32

    // issue chunk 0
    {
        const float* xa = X + (size_t)(bm + crow) * K;
        const float* wb = W + (size_t)(bn + crow) * K;
        uint32_t sa = sbase + SM_A(0) + crow * RPB;
        uint32_t sb = sbase + SM_B(0) + crow * RPB;
#pragma unroll
        for (int c = 0; c < 4; c++) {
            int ch = cbase + c;
            cp_async16(sa + ch * 16, xa + ch * 4);
            cp_async16(sb + ch * 16, wb + ch * 4);
        }
        cp_commit();
    }

    for (int ck = 0; ck < nchunks; ck++) {
        const int p = ck & 1;
        if (ck + 1 < nchunks) {
            const int k0 = (ck + 1) * GBK;
            const float* xa = X + (size_t)(bm + crow) * K + k0;
            const float* wb = W + (size_t)(bn + crow) * K + k0;
            uint32_t sa = sbase + SM_A((ck + 1) & 1) + crow * RPB;
            uint32_t sb = sbase + SM_B((ck + 1) & 1) + crow * RPB;
#pragma unroll
            for (int c = 0; c < 4; c++) {
                int ch = cbase + c;
                cp_async16(sa + ch * 16, xa + ch * 4);
                cp_async16(sb + ch * 16, wb + ch * 4);
            }
            cp_commit();
            cp_wait<1>();
        } else {
            cp_wait<0>();
        }
        __syncthreads();

        const float* As = (const float*)(smem + SM_A(p));
        const float* Bs = (const float*)(smem + SM_B(p));

#pragma unroll
        for (int ks = 0; ks < 4; ks++) {
            const int kk = ks * 8;
            uint32_t a[4][4], b[4][2];
#pragma unroll
            for (int ma = 0; ma < 4; ma++) {
                int r = wm + ma * 16 + g;
                a[ma][0] = f32_to_tf32(As[(size_t)r * RPF + kk + tg]);
                a[ma][1] = f32_to_tf32(As[(size_t)(r + 8) * RPF + kk + tg]);
                a[ma][2] = f32_to_tf32(As[(size_t)r * RPF + kk + tg + 4]);
                a[ma][3] = f32_to_tf32(As[(size_t)(r + 8) * RPF + kk + tg + 4]);
            }
#pragma unroll
            for (int na = 0; na < 4; na++) {
                int cl = wn + na * 8 + g;
                b[na][0] = f32_to_tf32(Bs[(size_t)cl * RPF + kk + tg]);
                b[na][1] = f32_to_tf32(Bs[(size_t)cl * RPF + kk + tg + 4]);
            }
#pragma unroll
            for (int ma = 0; ma < 4; ma++)
#pragma unroll
                for (int na = 0; na < 4; na++)
                    mma_tf32_16x8x8(acc[ma][na], a[ma], b[na]);
        }
        __syncthreads();
    }

#pragma unroll
    for (int ma = 0; ma < 4; ma++) {
        int row0 = bm + wm + ma * 16 + g;
#pragma unroll
        for (int na = 0; na < 4; na++) {
            int col = bn + wn + na * 8 + tg * 2;
            *(float2*)&C[(size_t)row0 * N + col] =
                make_float2(acc[ma][na][0], acc[ma][na][1]);
            *(float2*)&C[(size_t)(row0 + 8) * N + col] =
                make_float2(acc[ma][na][2], acc[ma][na][3]);
        }
    }
}

// ===========================================================================
// Causal flash attention with mma.sync tf32 (unchanged from R4).
// ===========================================================================
__global__ void __launch_bounds__(128) flash_mma(const float* __restrict__ qg,
                                                 const float* __restrict__ kg,
                                                 const float* __restrict__ vg,
                                                 float* __restrict__ og)
{
    __shared__ uint32_t Ks[64][68];
    __shared__ uint32_t Vs[64][72];

    const int qt   = blockIdx.x;
    const int h    = blockIdx.y;
    const int b    = blockIdx.z;
    const int t    = threadIdx.x;
    const int lane = t & 31;
    const int w    = t >> 5;
    const int g    = lane >> 2;
    const int tg   = lane & 3;
    const int r0   = w * 16 + g;
    const int r1   = r0 + 8;

    const float* qb = qg + ((size_t)(b * SEQ + qt * 64)) * DM + h * DK;
    const float* kb = kg + (size_t)b * SEQ * DM + h * DK;
    const float* vb = vg + (size_t)b * SEQ * DM + h * DK;

#pragma unroll
    for (int i = 0; i < 8; i++) {
        int idx = t + i * 128;
        int row = idx >> 4;
        int c4  = (idx & 15) * 4;
        float4 v = *(const float4*)(qb + (size_t)row * DM + c4);
        *(uint4*)&Ks[row][c4] = make_uint4(f32_to_tf32(v.x * 0.125f),
                                           f32_to_tf32(v.y * 0.125f),
                                           f32_to_tf32(v.z * 0.125f),
                                           f32_to_tf32(v.w * 0.125f));
    }
    __syncthreads();

    uint32_t qa[8][4];
#pragma unroll
    for (int ka = 0; ka < 8; ka++) {
        qa[ka][0] = Ks[r0][8 * ka + tg];
        qa[ka][1] = Ks[r1][8 * ka + tg];
        qa[ka][2] = Ks[r0][8 * ka + tg + 4];
        qa[ka][3] = Ks[r1][8 * ka + tg + 4];
    }

    float oacc[8][4];
#pragma unroll
    for (int na = 0; na < 8; na++)
#pragma unroll
        for (int j = 0; j < 4; j++) oacc[na][j] = 0.f;
    float m0 = -1e30f, m1 = -1e30f, l0 = 0.f, l1 = 0.f;

    for (int kt = 0; kt <= qt; kt++) {
        __syncthreads();

#pragma unroll
        for (int i = 0; i < 8; i++) {
            int idx = t + i * 128;
            int row = idx >> 4;
            int c4  = (idx & 15) * 4;
            const float* kp = kb + (size_t)(kt * 64 + row) * DM + c4;
            const float* vp = vb + (size_t)(kt * 64 + row) * DM + c4;
            float4 kv = *(const float4*)kp;
            float4 vv = *(const float4*)vp;
            *(uint4*)&Ks[row][c4] = make_uint4(f32_to_tf32(kv.x), f32_to_tf32(kv.y),
                                               f32_to_tf32(kv.z), f32_to_tf32(kv.w));
            *(uint4*)&Vs[row][c4] = make_uint4(f32_to_tf32(vv.x), f32_to_tf32(vv.y),
                                               f32_to_tf32(vv.z), f32_to_tf32(vv.w));
        }
        __syncthreads();

        float sacc[8][4];
#pragma unroll
        for (int na = 0; na < 8; na++)
#pragma unroll
            for (int j = 0; j < 4; j++) sacc[na][j] = 0.f;

#pragma unroll
        for (int ka = 0; ka < 8; ka++) {
#pragma unroll
            for (int na = 0; na < 8; na++) {
                uint32_t bf[2];
                bf[0] = Ks[8 * na + g][8 * ka + tg];
                bf[1] = Ks[8 * na + g][8 * ka + tg + 4];
                mma_tf32_16x8x8(sacc[na], qa[ka], bf);
            }
        }

        if (kt == qt) {
#pragma unroll
            for (int na = 0; na < 8; na++) {
                int c0 = 8 * na + 2 * tg;
                if (c0     > r0) sacc[na][0] = -1e30f;
                if (c0 + 1 > r0) sacc[na][1] = -1e30f;
                if (c0     > r1) sacc[na][2] = -1e30f;
                if (c0 + 1 > r1) sacc[na][3] = -1e30f;
            }
        }

        float mx0 = -1e30f, mx1 = -1e30f;
#pragma unroll
        for (int na = 0; na < 8; na++) {
            mx0 = fmaxf(mx0, fmaxf(sacc[na][0], sacc[na][1]));
            mx1 = fmaxf(mx1, fmaxf(sacc[na][2], sacc[na][3]));
        }
        mx0 = fmaxf(mx0, __shfl_xor_sync(0xffffffffu, mx0, 1));
        mx0 = fmaxf(mx0, __shfl_xor_sync(0xffffffffu, mx0, 2));
        mx1 = fmaxf(mx1, __shfl_xor_sync(0xffffffffu, mx1, 1));
        mx1 = fmaxf(mx1, __shfl_xor_sync(0xffffffffu, mx1, 2));

        float m0n = fmaxf(m0, mx0);
        float m1n = fmaxf(m1, mx1);
        float c0f = __expf(m0 - m0n);
        float c1f = __expf(m1 - m1n);
        float s0 = 0.f, s1 = 0.f;
#pragma unroll
        for (int na = 0; na < 8; na++) {
            sacc[na][0] = __expf(sacc[na][0] - m0n);
            sacc[na][1] = __expf(sacc[na][1] - m0n);
            sacc[na][2] = __expf(sacc[na][2] - m1n);
            sacc[na][3] = __expf(sacc[na][3] - m1n);
            s0 += sacc[na][0] + sacc[na][1];
            s1 += sacc[na][2] + sacc[na][3];
        }
        s0 += __shfl_xor_sync(0xffffffffu, s0, 1);
        s0 += __shfl_xor_sync(0xffffffffu, s0, 2);
        s1 += __shfl_xor_sync(0xffffffffu, s1, 1);
        s1 += __shfl_xor_sync(0xffffffffu, s1, 2);
        l0 = l0 * c0f + s0;
        l1 = l1 * c1f + s1;
        m0 = m0n;
        m1 = m1n;
#pragma unroll
        for (int na = 0; na < 8; na++) {
            oacc[na][0] *= c0f; oacc[na][1] *= c0f;
            oacc[na][2] *= c1f; oacc[na][3] *= c1f;
        }

        __syncthreads();
#pragma unroll
        for (int na = 0; na < 8; na++) {
            int cc = 8 * na + 2 * tg;
            *(uint2*)&Ks[r0][cc] = make_uint2(f32_to_tf32(sacc[na][0]),
                                              f32_to_tf32(sacc[na][1]));
            *(uint2*)&Ks[r1][cc] = make_uint2(f32_to_tf32(sacc[na][2]),
                                              f32_to_tf32(sacc[na][3]));
        }
        __syncthreads();

#pragma unroll
        for (int ka = 0; ka < 8; ka++) {
            uint32_t pa[4];
            pa[0] = Ks[r0][8 * ka + tg];
            pa[1] = Ks[r1][8 * ka + tg];
            pa[2] = Ks[r0][8 * ka + tg + 4];
            pa[3] = Ks[r1][8 * ka + tg + 4];
#pragma unroll
            for (int na = 0; na < 8; na++) {
                uint32_t bf[2];
                bf[0] = Vs[8 * ka + tg][8 * na + g];
                bf[1] = Vs[8 * ka + tg + 4][8 * na + g];
                mma_tf32_16x8x8(oacc[na], pa, bf);
            }
        }
    }

    float inv0 = 1.f / l0;
    float inv1 = 1.f / l1;
    float* ob = og + ((size_t)(b * SEQ + qt * 64)) * DM + h * DK;
#pragma unroll
    for (int na = 0; na < 8; na++) {
        int col = 8 * na + 2 * tg;
        *(float2*)(ob + (size_t)r0 * DM + col) =
            make_float2(oacc[na][0] * inv0, oacc[na][1] * inv0);
        *(float2*)(ob + (size_t)r1 * DM + col) =
            make_float2(oacc[na][2] * inv1, oacc[na][3] * inv1);
    }
}

// ---------------------------------------------------------------------------

extern "C" void kernel_launch(void* const* d_in, const int* in_sizes, int n_in,
                              void* d_out, int out_size)
{
    (void)in_sizes; (void)n_in; (void)out_size;
    const float* Q  = (const float*)d_in[0];
    const float* K  = (const float*)d_in[1];
    const float* V  = (const float*)d_in[2];
    const float* wq = (const float*)d_in[3];
    const float* wk = (const float*)d_in[4];
    const float* wv = (const float*)d_in[5];
    const float* wo = (const float*)d_in[6];
    float* out = (float*)d_out;

    float *gq, *gk, *gv, *ga;
    cudaGetSymbolAddress((void**)&gq, g_q);
    cudaGetSymbolAddress((void**)&gk, g_k);
    cudaGetSymbolAddress((void**)&gv, g_v);
    cudaGetSymbolAddress((void**)&ga, g_attn);

    cudaFuncSetAttribute(gemm_pipe,
                         cudaFuncAttributeMaxDynamicSharedMemorySize,
                         GEMM_SMEM);

    dim3 qkv_grid(DM / GBN, MROWS / GBM, 3);   // (8, 64, 3)
    gemm_pipe<<<qkv_grid, 256, GEMM_SMEM>>>(Q, K, V, wq, wk, wv, gq, gk, gv,
                                            MROWS, DM, DM);

    flash_mma<<<dim3(SEQ / 64, NH, NB), 128>>>(gq, gk, gv, ga);

    dim3 o_grid(DM / GBN, MROWS / GBM, 1);
    gemm_pipe<<<o_grid, 256, GEMM_SMEM>>>(ga, ga, ga, wo, wo, wo, out, out, out,
                                          MROWS, DM, DM);
}